// round 3
// baseline (speedup 1.0000x reference)
#include <cuda_runtime.h>
#include <cstdint>

#define B_   64
#define S_   2048
#define RNN_ 1024
#define ATT_ 512
#define CTX_ 1024
#define MIN_VALUE_ -100000000.0f

#define NCHUNK 16
#define SCHUNK (S_ / NCHUNK)   // 128

// Scratch (no allocations allowed in kernel_launch)
__device__ float g_attn_h[B_ * ATT_];
__device__ float g_scores[B_ * S_];
__device__ float g_partial[NCHUNK * B_ * CTX_];

// ---------------------------------------------------------------------------
// Kernel 1: attn_h[b,a] = sum_k h[b,k] * W[a,k] + bias[a]
// Tiled GEMM: BM=64 (all of B), BN=64, BK=32. Grid = ATT/64 = 8 blocks.
// ---------------------------------------------------------------------------
#define BM 64
#define BN 64
#define BK 32
__global__ __launch_bounds__(256) void attn_h_kernel(
    const float* __restrict__ h, const float* __restrict__ W,
    const float* __restrict__ bias) {
    __shared__ float As[BM][BK + 1];
    __shared__ float Bs[BN][BK + 1];
    const int a0 = blockIdx.x * BN;
    const int tx = threadIdx.x & 15;   // a sub-tile
    const int ty = threadIdx.x >> 4;   // b sub-tile
    float acc[4][4] = {};

    for (int k0 = 0; k0 < RNN_; k0 += BK) {
        for (int i = threadIdx.x; i < BM * BK; i += 256) {
            int r = i >> 5, c = i & 31;
            As[r][c] = h[r * RNN_ + k0 + c];
        }
        for (int i = threadIdx.x; i < BN * BK; i += 256) {
            int r = i >> 5, c = i & 31;
            Bs[r][c] = W[(a0 + r) * RNN_ + k0 + c];
        }
        __syncthreads();
#pragma unroll
        for (int k = 0; k < BK; k++) {
            float av[4], bv[4];
#pragma unroll
            for (int i = 0; i < 4; i++) av[i] = As[ty * 4 + i][k];
#pragma unroll
            for (int j = 0; j < 4; j++) bv[j] = Bs[tx * 4 + j][k];
#pragma unroll
            for (int i = 0; i < 4; i++)
#pragma unroll
                for (int j = 0; j < 4; j++)
                    acc[i][j] = fmaf(av[i], bv[j], acc[i][j]);
        }
        __syncthreads();
    }
#pragma unroll
    for (int i = 0; i < 4; i++)
#pragma unroll
        for (int j = 0; j < 4; j++)
            g_attn_h[(ty * 4 + i) * ATT_ + a0 + tx * 4 + j] =
                acc[i][j] + bias[a0 + tx * 4 + j];
}

// ---------------------------------------------------------------------------
// Accurate fast tanh: 1 - 2/(exp(2x)+1).  Handles +/-inf saturation naturally.
// ---------------------------------------------------------------------------
__device__ __forceinline__ float fast_tanh(float x) {
    float e = __expf(2.0f * x);
    return 1.0f - __fdividef(2.0f, e + 1.0f);
}

// ---------------------------------------------------------------------------
// Kernel 2: scores[b,s] = sum_a tanh(pc[b,s,a] + attn_h[b,a]) * w_alpha[a]
//           + b_alpha, masked -> MIN_VALUE.
// One warp per (b,s) row. ATT=512 floats = 128 float4 = 32 lanes x 4.
// mask is read as 4-byte words (bool promoted to int32/float32 by the
// harness): nonzero bits == True for either encoding.
// ---------------------------------------------------------------------------
__global__ __launch_bounds__(256) void scores_kernel(
    const float4* __restrict__ pc, const uint32_t* __restrict__ mask,
    const float4* __restrict__ w_alpha, const float* __restrict__ b_alpha) {
    const int row  = (blockIdx.x * blockDim.x + threadIdx.x) >> 5;
    const int lane = threadIdx.x & 31;
    const int b    = row >> 11;  // S = 2048
    const float4* prow = pc + (size_t)row * (ATT_ / 4);
    const float4* ah   = (const float4*)g_attn_h + b * (ATT_ / 4);
    float sum = 0.0f;
#pragma unroll
    for (int i = 0; i < 4; i++) {
        int idx = lane + i * 32;
        float4 p = prow[idx];
        float4 a = ah[idx];
        float4 w = w_alpha[idx];
        sum += fast_tanh(p.x + a.x) * w.x;
        sum += fast_tanh(p.y + a.y) * w.y;
        sum += fast_tanh(p.z + a.z) * w.z;
        sum += fast_tanh(p.w + a.w) * w.w;
    }
#pragma unroll
    for (int off = 16; off; off >>= 1)
        sum += __shfl_xor_sync(0xFFFFFFFFu, sum, off);
    if (lane == 0) {
        g_scores[row] = (mask[row] != 0u) ? MIN_VALUE_ : (sum + b_alpha[0]);
    }
}

// ---------------------------------------------------------------------------
// Kernel 3: softmax over S per batch row. 64 blocks x 256 threads (8 elems/thr)
// Writes attn directly into the output buffer slot.
// ---------------------------------------------------------------------------
__global__ __launch_bounds__(256) void softmax_kernel(float* __restrict__ attn_out) {
    const int b = blockIdx.x;
    const float* row = g_scores + b * S_;
    float* out = attn_out + b * S_;
    __shared__ float red[256];

    float vals[8];
    float m = -3.402823466e+38f;
#pragma unroll
    for (int i = 0; i < 8; i++) {
        vals[i] = row[threadIdx.x + i * 256];
        m = fmaxf(m, vals[i]);
    }
    red[threadIdx.x] = m;
    __syncthreads();
    for (int off = 128; off; off >>= 1) {
        if (threadIdx.x < off)
            red[threadIdx.x] = fmaxf(red[threadIdx.x], red[threadIdx.x + off]);
        __syncthreads();
    }
    m = red[0];
    __syncthreads();

    float sum = 0.0f;
#pragma unroll
    for (int i = 0; i < 8; i++) {
        vals[i] = __expf(vals[i] - m);
        sum += vals[i];
    }
    red[threadIdx.x] = sum;
    __syncthreads();
    for (int off = 128; off; off >>= 1) {
        if (threadIdx.x < off)
            red[threadIdx.x] += red[threadIdx.x + off];
        __syncthreads();
    }
    float inv = __fdividef(1.0f, red[0]);
#pragma unroll
    for (int i = 0; i < 8; i++)
        out[threadIdx.x + i * 256] = vals[i] * inv;
}

// ---------------------------------------------------------------------------
// Kernel 4: partial weighted context.
// Grid (NCHUNK, B): each block streams context[b, s0:s0+SCHUNK, :] (512 KB)
// and accumulates a [CTX] partial in registers (float4/thread, 256 threads).
// ---------------------------------------------------------------------------
__global__ __launch_bounds__(256) void wctx_kernel(
    const float4* __restrict__ context, const float* __restrict__ attn) {
    const int b = blockIdx.y;
    const int chunk = blockIdx.x;
    const int s0 = chunk * SCHUNK;
    __shared__ float w[SCHUNK];
    if (threadIdx.x < SCHUNK)
        w[threadIdx.x] = attn[b * S_ + s0 + threadIdx.x];
    __syncthreads();

    const float4* ctx = context + ((size_t)b * S_ + s0) * (CTX_ / 4);
    const int t = threadIdx.x;
    float4 acc = make_float4(0.f, 0.f, 0.f, 0.f);
#pragma unroll 8
    for (int s = 0; s < SCHUNK; s++) {
        float4 v = ctx[(size_t)s * (CTX_ / 4) + t];
        float ww = w[s];
        acc.x = fmaf(ww, v.x, acc.x);
        acc.y = fmaf(ww, v.y, acc.y);
        acc.z = fmaf(ww, v.z, acc.z);
        acc.w = fmaf(ww, v.w, acc.w);
    }
    ((float4*)g_partial)[((size_t)chunk * B_ + b) * (CTX_ / 4) + t] = acc;
}

// ---------------------------------------------------------------------------
// Kernel 5: deterministic reduce of the NCHUNK partials -> weighted_context.
// ---------------------------------------------------------------------------
__global__ __launch_bounds__(256) void reduce_kernel(float* __restrict__ wout) {
    const int b = blockIdx.x;
    const int t = threadIdx.x;
    const float4* part = (const float4*)g_partial;
    float4 acc = make_float4(0.f, 0.f, 0.f, 0.f);
#pragma unroll
    for (int c = 0; c < NCHUNK; c++) {
        float4 v = part[((size_t)c * B_ + b) * (CTX_ / 4) + t];
        acc.x += v.x; acc.y += v.y; acc.z += v.z; acc.w += v.w;
    }
    ((float4*)wout)[b * (CTX_ / 4) + t] = acc;
}

// ---------------------------------------------------------------------------
extern "C" void kernel_launch(void* const* d_in, const int* in_sizes, int n_in,
                              void* d_out, int out_size) {
    const float*    h    = (const float*)d_in[0];
    const float*    pc   = (const float*)d_in[1];
    const float*    ctx  = (const float*)d_in[2];
    const uint32_t* mask = (const uint32_t*)d_in[3];
    const float*    W    = (const float*)d_in[4];
    const float*    bh   = (const float*)d_in[5];
    const float*    wa   = (const float*)d_in[6];
    const float*    ba   = (const float*)d_in[7];

    float* out      = (float*)d_out;
    float* wctx_out = out;               // [B, CTX]
    float* attn_out = out + B_ * CTX_;   // [B, S]

    attn_h_kernel<<<ATT_ / BN, 256>>>(h, W, bh);
    scores_kernel<<<(B_ * S_) / 8, 256>>>((const float4*)pc, mask,
                                          (const float4*)wa, ba);
    softmax_kernel<<<B_, 256>>>(attn_out);
    wctx_kernel<<<dim3(NCHUNK, B_), 256>>>((const float4*)ctx, attn_out);
    reduce_kernel<<<B_, 256>>>(wctx_out);
}

// round 4
// speedup vs baseline: 1.5372x; 1.5372x over previous
#include <cuda_runtime.h>
#include <cstdint>

#define B_   64
#define S_   2048
#define RNN_ 1024
#define ATT_ 512
#define CTX_ 1024
#define MIN_VALUE_ -100000000.0f

#define NCHUNK 32
#define SCHUNK (S_ / NCHUNK)   // 64

#define KSPLIT 8
#define KCHUNK (RNN_ / KSPLIT) // 128

// Scratch (no allocations allowed in kernel_launch)
__device__ float g_attn_part[KSPLIT * B_ * ATT_];
__device__ float g_attn_h[B_ * ATT_];
__device__ float g_scores[B_ * S_];
__device__ float g_partial[NCHUNK * B_ * CTX_];

// ---------------------------------------------------------------------------
// Kernel 1: split-K GEMM partials.
// grid = (ATT/64 = 8 n-tiles, KSPLIT = 8 k-chunks) = 64 blocks.
// Each block computes partial[k][b, a0:a0+64] over its 128-wide K chunk.
// ---------------------------------------------------------------------------
#define BM 64
#define BN 64
#define BK 32
__global__ __launch_bounds__(256) void attn_h_kernel(
    const float* __restrict__ h, const float* __restrict__ W) {
    __shared__ float As[BM][BK + 1];
    __shared__ float Bs[BN][BK + 1];
    const int a0 = blockIdx.x * BN;
    const int kbase = blockIdx.y * KCHUNK;
    const int tx = threadIdx.x & 15;   // a sub-tile
    const int ty = threadIdx.x >> 4;   // b sub-tile
    float acc[4][4] = {};

    for (int k0 = kbase; k0 < kbase + KCHUNK; k0 += BK) {
        for (int i = threadIdx.x; i < BM * BK; i += 256) {
            int r = i >> 5, c = i & 31;
            As[r][c] = h[r * RNN_ + k0 + c];
        }
        for (int i = threadIdx.x; i < BN * BK; i += 256) {
            int r = i >> 5, c = i & 31;
            Bs[r][c] = W[(a0 + r) * RNN_ + k0 + c];
        }
        __syncthreads();
#pragma unroll
        for (int k = 0; k < BK; k++) {
            float av[4], bv[4];
#pragma unroll
            for (int i = 0; i < 4; i++) av[i] = As[ty * 4 + i][k];
#pragma unroll
            for (int j = 0; j < 4; j++) bv[j] = Bs[tx * 4 + j][k];
#pragma unroll
            for (int i = 0; i < 4; i++)
#pragma unroll
                for (int j = 0; j < 4; j++)
                    acc[i][j] = fmaf(av[i], bv[j], acc[i][j]);
        }
        __syncthreads();
    }
    float* part = g_attn_part + (size_t)blockIdx.y * B_ * ATT_;
#pragma unroll
    for (int i = 0; i < 4; i++)
#pragma unroll
        for (int j = 0; j < 4; j++)
            part[(ty * 4 + i) * ATT_ + a0 + tx * 4 + j] = acc[i][j];
}

// ---------------------------------------------------------------------------
// Kernel 1b: reduce split-K partials + bias -> attn_h. 32768 elems.
// ---------------------------------------------------------------------------
__global__ __launch_bounds__(256) void reduce_attn_kernel(
    const float* __restrict__ bias) {
    const int idx = blockIdx.x * 256 + threadIdx.x;   // 128 blocks
    const int a = idx & (ATT_ - 1);
    float s = bias[a];
#pragma unroll
    for (int k = 0; k < KSPLIT; k++)
        s += g_attn_part[(size_t)k * B_ * ATT_ + idx];
    g_attn_h[idx] = s;
}

// ---------------------------------------------------------------------------
// Accurate fast tanh: 1 - 2/(exp(2x)+1).  Handles +/-inf saturation naturally.
// ---------------------------------------------------------------------------
__device__ __forceinline__ float fast_tanh(float x) {
    float e = __expf(2.0f * x);
    return 1.0f - __fdividef(2.0f, e + 1.0f);
}

// ---------------------------------------------------------------------------
// Kernel 2: scores[b,s] = sum_a tanh(pc[b,s,a] + attn_h[b,a]) * w_alpha[a]
//           + b_alpha, masked -> MIN_VALUE.
// One warp per (b,s) row. ATT=512 floats = 128 float4 = 32 lanes x 4.
// mask read as 4-byte words (bool promoted by harness); nonzero == True.
// ---------------------------------------------------------------------------
__global__ __launch_bounds__(256) void scores_kernel(
    const float4* __restrict__ pc, const uint32_t* __restrict__ mask,
    const float4* __restrict__ w_alpha, const float* __restrict__ b_alpha) {
    const int row  = (blockIdx.x * blockDim.x + threadIdx.x) >> 5;
    const int lane = threadIdx.x & 31;
    const int b    = row >> 11;  // S = 2048
    const float4* prow = pc + (size_t)row * (ATT_ / 4);
    const float4* ah   = (const float4*)g_attn_h + b * (ATT_ / 4);
    float sum = 0.0f;
#pragma unroll
    for (int i = 0; i < 4; i++) {
        int idx = lane + i * 32;
        float4 p = prow[idx];
        float4 a = ah[idx];
        float4 w = w_alpha[idx];
        sum += fast_tanh(p.x + a.x) * w.x;
        sum += fast_tanh(p.y + a.y) * w.y;
        sum += fast_tanh(p.z + a.z) * w.z;
        sum += fast_tanh(p.w + a.w) * w.w;
    }
#pragma unroll
    for (int off = 16; off; off >>= 1)
        sum += __shfl_xor_sync(0xFFFFFFFFu, sum, off);
    if (lane == 0) {
        g_scores[row] = (mask[row] != 0u) ? MIN_VALUE_ : (sum + b_alpha[0]);
    }
}

// ---------------------------------------------------------------------------
// Kernel 3: softmax over S per batch row. 64 blocks x 256 threads (8 elems/thr)
// Writes attn directly into the output buffer slot.
// ---------------------------------------------------------------------------
__global__ __launch_bounds__(256) void softmax_kernel(float* __restrict__ attn_out) {
    const int b = blockIdx.x;
    const float* row = g_scores + b * S_;
    float* out = attn_out + b * S_;
    __shared__ float red[256];

    float vals[8];
    float m = -3.402823466e+38f;
#pragma unroll
    for (int i = 0; i < 8; i++) {
        vals[i] = row[threadIdx.x + i * 256];
        m = fmaxf(m, vals[i]);
    }
    red[threadIdx.x] = m;
    __syncthreads();
    for (int off = 128; off; off >>= 1) {
        if (threadIdx.x < off)
            red[threadIdx.x] = fmaxf(red[threadIdx.x], red[threadIdx.x + off]);
        __syncthreads();
    }
    m = red[0];
    __syncthreads();

    float sum = 0.0f;
#pragma unroll
    for (int i = 0; i < 8; i++) {
        vals[i] = __expf(vals[i] - m);
        sum += vals[i];
    }
    red[threadIdx.x] = sum;
    __syncthreads();
    for (int off = 128; off; off >>= 1) {
        if (threadIdx.x < off)
            red[threadIdx.x] += red[threadIdx.x + off];
        __syncthreads();
    }
    float inv = __fdividef(1.0f, red[0]);
#pragma unroll
    for (int i = 0; i < 8; i++)
        out[threadIdx.x + i * 256] = vals[i] * inv;
}

// ---------------------------------------------------------------------------
// Kernel 4: partial weighted context.
// Grid (NCHUNK, B): each block streams context[b, s0:s0+SCHUNK, :] (256 KB)
// and accumulates a [CTX] partial in registers (float4/thread, 256 threads).
// ---------------------------------------------------------------------------
__global__ __launch_bounds__(256) void wctx_kernel(
    const float4* __restrict__ context, const float* __restrict__ attn) {
    const int b = blockIdx.y;
    const int chunk = blockIdx.x;
    const int s0 = chunk * SCHUNK;
    __shared__ float w[SCHUNK];
    if (threadIdx.x < SCHUNK)
        w[threadIdx.x] = attn[b * S_ + s0 + threadIdx.x];
    __syncthreads();

    const float4* ctx = context + ((size_t)b * S_ + s0) * (CTX_ / 4);
    const int t = threadIdx.x;
    float4 acc = make_float4(0.f, 0.f, 0.f, 0.f);
#pragma unroll 8
    for (int s = 0; s < SCHUNK; s++) {
        float4 v = ctx[(size_t)s * (CTX_ / 4) + t];
        float ww = w[s];
        acc.x = fmaf(ww, v.x, acc.x);
        acc.y = fmaf(ww, v.y, acc.y);
        acc.z = fmaf(ww, v.z, acc.z);
        acc.w = fmaf(ww, v.w, acc.w);
    }
    ((float4*)g_partial)[((size_t)chunk * B_ + b) * (CTX_ / 4) + t] = acc;
}

// ---------------------------------------------------------------------------
// Kernel 5: deterministic reduce of the NCHUNK partials -> weighted_context.
// ---------------------------------------------------------------------------
__global__ __launch_bounds__(256) void reduce_kernel(float* __restrict__ wout) {
    const int b = blockIdx.x;
    const int t = threadIdx.x;
    const float4* part = (const float4*)g_partial;
    float4 acc = make_float4(0.f, 0.f, 0.f, 0.f);
#pragma unroll
    for (int c = 0; c < NCHUNK; c++) {
        float4 v = part[((size_t)c * B_ + b) * (CTX_ / 4) + t];
        acc.x += v.x; acc.y += v.y; acc.z += v.z; acc.w += v.w;
    }
    ((float4*)wout)[b * (CTX_ / 4) + t] = acc;
}

// ---------------------------------------------------------------------------
extern "C" void kernel_launch(void* const* d_in, const int* in_sizes, int n_in,
                              void* d_out, int out_size) {
    const float*    h    = (const float*)d_in[0];
    const float*    pc   = (const float*)d_in[1];
    const float*    ctx  = (const float*)d_in[2];
    const uint32_t* mask = (const uint32_t*)d_in[3];
    const float*    W    = (const float*)d_in[4];
    const float*    bh   = (const float*)d_in[5];
    const float*    wa   = (const float*)d_in[6];
    const float*    ba   = (const float*)d_in[7];

    float* out      = (float*)d_out;
    float* wctx_out = out;               // [B, CTX]
    float* attn_out = out + B_ * CTX_;   // [B, S]

    attn_h_kernel<<<dim3(ATT_ / BN, KSPLIT), 256>>>(h, W);
    reduce_attn_kernel<<<(B_ * ATT_) / 256, 256>>>(bh);
    scores_kernel<<<(B_ * S_) / 8, 256>>>((const float4*)pc, mask,
                                          (const float4*)wa, ba);
    softmax_kernel<<<B_, 256>>>(attn_out);
    wctx_kernel<<<dim3(NCHUNK, B_), 256>>>((const float4*)ctx, attn_out);
    reduce_kernel<<<B_, 256>>>(wctx_out);
}

// round 5
// speedup vs baseline: 1.6579x; 1.0786x over previous
#include <cuda_runtime.h>
#include <cstdint>

#define B_   64
#define S_   2048
#define RNN_ 1024
#define ATT_ 512
#define CTX_ 1024
#define MIN_VALUE_ -100000000.0f

#define NCHUNK 32
#define SCHUNK (S_ / NCHUNK)   // 64

#define KSPLIT 16
#define KCHUNK (RNN_ / KSPLIT) // 64

// Scratch (no allocations allowed in kernel_launch)
__device__ float g_attn_part[KSPLIT * B_ * ATT_];
__device__ float g_attn_h[B_ * ATT_];
__device__ float g_scores[B_ * S_];
__device__ float g_partial[NCHUNK * B_ * CTX_];

// ---------------------------------------------------------------------------
// Kernel 1: split-K GEMM partials.
// grid = (ATT/64 = 8 n-tiles, KSPLIT = 16 k-chunks) = 128 blocks.
// ---------------------------------------------------------------------------
#define BM 64
#define BN 64
#define BK 32
__global__ __launch_bounds__(256) void attn_h_kernel(
    const float* __restrict__ h, const float* __restrict__ W) {
    __shared__ float As[BM][BK + 1];
    __shared__ float Bs[BN][BK + 1];
    const int a0 = blockIdx.x * BN;
    const int kbase = blockIdx.y * KCHUNK;
    const int tx = threadIdx.x & 15;   // a sub-tile
    const int ty = threadIdx.x >> 4;   // b sub-tile
    float acc[4][4] = {};

    for (int k0 = kbase; k0 < kbase + KCHUNK; k0 += BK) {
        for (int i = threadIdx.x; i < BM * BK; i += 256) {
            int r = i >> 5, c = i & 31;
            As[r][c] = h[r * RNN_ + k0 + c];
        }
        for (int i = threadIdx.x; i < BN * BK; i += 256) {
            int r = i >> 5, c = i & 31;
            Bs[r][c] = W[(a0 + r) * RNN_ + k0 + c];
        }
        __syncthreads();
#pragma unroll
        for (int k = 0; k < BK; k++) {
            float av[4], bv[4];
#pragma unroll
            for (int i = 0; i < 4; i++) av[i] = As[ty * 4 + i][k];
#pragma unroll
            for (int j = 0; j < 4; j++) bv[j] = Bs[tx * 4 + j][k];
#pragma unroll
            for (int i = 0; i < 4; i++)
#pragma unroll
                for (int j = 0; j < 4; j++)
                    acc[i][j] = fmaf(av[i], bv[j], acc[i][j]);
        }
        __syncthreads();
    }
    float* part = g_attn_part + (size_t)blockIdx.y * B_ * ATT_;
#pragma unroll
    for (int i = 0; i < 4; i++)
#pragma unroll
        for (int j = 0; j < 4; j++)
            part[(ty * 4 + i) * ATT_ + a0 + tx * 4 + j] = acc[i][j];
}

// ---------------------------------------------------------------------------
// Kernel 1b: reduce split-K partials + bias -> attn_h.
// ---------------------------------------------------------------------------
__global__ __launch_bounds__(256) void reduce_attn_kernel(
    const float* __restrict__ bias) {
    const int idx = blockIdx.x * 256 + threadIdx.x;   // 128 blocks
    const int a = idx & (ATT_ - 1);
    float s = bias[a];
#pragma unroll
    for (int k = 0; k < KSPLIT; k++)
        s += g_attn_part[(size_t)k * B_ * ATT_ + idx];
    g_attn_h[idx] = s;
}

// ---------------------------------------------------------------------------
// Accurate fast tanh: 1 - 2/(exp(2x)+1).  Handles +/-inf saturation naturally.
// ---------------------------------------------------------------------------
__device__ __forceinline__ float fast_tanh(float x) {
    float e = __expf(2.0f * x);
    return 1.0f - __fdividef(2.0f, e + 1.0f);
}

// ---------------------------------------------------------------------------
// Kernel 2: scores[b,s] = sum_a tanh(pc[b,s,a] + attn_h[b,a]) * w_alpha[a]
//           + b_alpha, masked -> MIN_VALUE.
// TWO consecutive rows per warp (same b): attn_h / w_alpha loads amortized,
// 8 independent streaming LDG.128 per iteration for MLP.
// mask read as 4-byte words (bool promoted by harness); nonzero == True.
// ---------------------------------------------------------------------------
__global__ __launch_bounds__(256) void scores_kernel(
    const float4* __restrict__ pc, const uint32_t* __restrict__ mask,
    const float4* __restrict__ w_alpha, const float* __restrict__ b_alpha) {
    const int warp = (blockIdx.x * blockDim.x + threadIdx.x) >> 5;
    const int lane = threadIdx.x & 31;
    const int r0   = warp * 2;          // rows r0, r0+1 (always same b)
    const int b    = r0 >> 11;          // S = 2048
    const float4* prow0 = pc + (size_t)r0 * (ATT_ / 4);
    const float4* prow1 = prow0 + (ATT_ / 4);
    const float4* ah    = (const float4*)g_attn_h + b * (ATT_ / 4);
    float sum0 = 0.0f, sum1 = 0.0f;
#pragma unroll
    for (int i = 0; i < 4; i++) {
        int idx = lane + i * 32;
        float4 p0 = __ldcs(prow0 + idx);
        float4 p1 = __ldcs(prow1 + idx);
        float4 a  = ah[idx];
        float4 w  = w_alpha[idx];
        sum0 += fast_tanh(p0.x + a.x) * w.x;
        sum0 += fast_tanh(p0.y + a.y) * w.y;
        sum0 += fast_tanh(p0.z + a.z) * w.z;
        sum0 += fast_tanh(p0.w + a.w) * w.w;
        sum1 += fast_tanh(p1.x + a.x) * w.x;
        sum1 += fast_tanh(p1.y + a.y) * w.y;
        sum1 += fast_tanh(p1.z + a.z) * w.z;
        sum1 += fast_tanh(p1.w + a.w) * w.w;
    }
#pragma unroll
    for (int off = 16; off; off >>= 1) {
        sum0 += __shfl_xor_sync(0xFFFFFFFFu, sum0, off);
        sum1 += __shfl_xor_sync(0xFFFFFFFFu, sum1, off);
    }
    if (lane == 0) {
        float ba = b_alpha[0];
        g_scores[r0]     = (mask[r0]     != 0u) ? MIN_VALUE_ : (sum0 + ba);
        g_scores[r0 + 1] = (mask[r0 + 1] != 0u) ? MIN_VALUE_ : (sum1 + ba);
    }
}

// ---------------------------------------------------------------------------
// Kernel 3: softmax over S per batch row, warp-shuffle reductions.
// 64 blocks x 256 threads (8 elems/thread). Writes attn into output slot.
// ---------------------------------------------------------------------------
__global__ __launch_bounds__(256) void softmax_kernel(float* __restrict__ attn_out) {
    const int b = blockIdx.x;
    const int t = threadIdx.x;
    const int lane = t & 31, wid = t >> 5;
    const float* row = g_scores + b * S_;
    float* out = attn_out + b * S_;
    __shared__ float red[8];

    float vals[8];
    float m = -3.402823466e+38f;
#pragma unroll
    for (int i = 0; i < 8; i++) {
        vals[i] = row[t + i * 256];
        m = fmaxf(m, vals[i]);
    }
#pragma unroll
    for (int off = 16; off; off >>= 1)
        m = fmaxf(m, __shfl_xor_sync(0xFFFFFFFFu, m, off));
    if (lane == 0) red[wid] = m;
    __syncthreads();
    if (wid == 0) {
        float v = red[lane & 7];
#pragma unroll
        for (int off = 4; off; off >>= 1)
            v = fmaxf(v, __shfl_xor_sync(0xFFFFFFFFu, v, off));
        if (lane == 0) red[0] = v;
    }
    __syncthreads();
    m = red[0];

    float sum = 0.0f;
#pragma unroll
    for (int i = 0; i < 8; i++) {
        vals[i] = __expf(vals[i] - m);
        sum += vals[i];
    }
#pragma unroll
    for (int off = 16; off; off >>= 1)
        sum += __shfl_xor_sync(0xFFFFFFFFu, sum, off);
    __syncthreads();           // red[] reuse
    if (lane == 0) red[wid] = sum;
    __syncthreads();
    if (wid == 0) {
        float v = red[lane & 7];
#pragma unroll
        for (int off = 4; off; off >>= 1)
            v += __shfl_xor_sync(0xFFFFFFFFu, v, off);
        if (lane == 0) red[0] = v;
    }
    __syncthreads();
    float inv = __fdividef(1.0f, red[0]);
#pragma unroll
    for (int i = 0; i < 8; i++)
        out[t + i * 256] = vals[i] * inv;
}

// ---------------------------------------------------------------------------
// Kernel 4: partial weighted context.
// Grid (NCHUNK, B): each block streams context[b, s0:s0+SCHUNK, :] (256 KB)
// with evict-first loads, accumulates a [CTX] partial (float4/thread).
// ---------------------------------------------------------------------------
__global__ __launch_bounds__(256) void wctx_kernel(
    const float4* __restrict__ context, const float* __restrict__ attn) {
    const int b = blockIdx.y;
    const int chunk = blockIdx.x;
    const int s0 = chunk * SCHUNK;
    __shared__ float w[SCHUNK];
    if (threadIdx.x < SCHUNK)
        w[threadIdx.x] = attn[b * S_ + s0 + threadIdx.x];
    __syncthreads();

    const float4* ctx = context + ((size_t)b * S_ + s0) * (CTX_ / 4);
    const int t = threadIdx.x;
    float4 acc = make_float4(0.f, 0.f, 0.f, 0.f);
#pragma unroll 8
    for (int s = 0; s < SCHUNK; s++) {
        float4 v = __ldcs(ctx + (size_t)s * (CTX_ / 4) + t);
        float ww = w[s];
        acc.x = fmaf(ww, v.x, acc.x);
        acc.y = fmaf(ww, v.y, acc.y);
        acc.z = fmaf(ww, v.z, acc.z);
        acc.w = fmaf(ww, v.w, acc.w);
    }
    ((float4*)g_partial)[((size_t)chunk * B_ + b) * (CTX_ / 4) + t] = acc;
}

// ---------------------------------------------------------------------------
// Kernel 5: deterministic reduce of the NCHUNK partials -> weighted_context.
// ---------------------------------------------------------------------------
__global__ __launch_bounds__(256) void reduce_kernel(float* __restrict__ wout) {
    const int b = blockIdx.x;
    const int t = threadIdx.x;
    const float4* part = (const float4*)g_partial;
    float4 acc = make_float4(0.f, 0.f, 0.f, 0.f);
#pragma unroll
    for (int c = 0; c < NCHUNK; c++) {
        float4 v = part[((size_t)c * B_ + b) * (CTX_ / 4) + t];
        acc.x += v.x; acc.y += v.y; acc.z += v.z; acc.w += v.w;
    }
    ((float4*)wout)[b * (CTX_ / 4) + t] = acc;
}

// ---------------------------------------------------------------------------
extern "C" void kernel_launch(void* const* d_in, const int* in_sizes, int n_in,
                              void* d_out, int out_size) {
    const float*    h    = (const float*)d_in[0];
    const float*    pc   = (const float*)d_in[1];
    const float*    ctx  = (const float*)d_in[2];
    const uint32_t* mask = (const uint32_t*)d_in[3];
    const float*    W    = (const float*)d_in[4];
    const float*    bh   = (const float*)d_in[5];
    const float*    wa   = (const float*)d_in[6];
    const float*    ba   = (const float*)d_in[7];

    float* out      = (float*)d_out;
    float* wctx_out = out;               // [B, CTX]
    float* attn_out = out + B_ * CTX_;   // [B, S]

    attn_h_kernel<<<dim3(ATT_ / BN, KSPLIT), 256>>>(h, W);
    reduce_attn_kernel<<<(B_ * ATT_) / 256, 256>>>(bh);
    scores_kernel<<<(B_ * S_) / 16, 256>>>((const float4*)pc, mask,
                                           (const float4*)wa, ba);
    softmax_kernel<<<B_, 256>>>(attn_out);
    wctx_kernel<<<dim3(NCHUNK, B_), 256>>>((const float4*)ctx, attn_out);
    reduce_kernel<<<B_, 256>>>(wctx_out);
}

// round 6
// speedup vs baseline: 1.6637x; 1.0035x over previous
#include <cuda_runtime.h>
#include <cstdint>

#define B_   64
#define S_   2048
#define RNN_ 1024
#define ATT_ 512
#define CTX_ 1024
#define MIN_VALUE_ -100000000.0f

#define NCHUNK 32
#define SCHUNK (S_ / NCHUNK)   // 64

#define KSPLIT 16
#define KCHUNK (RNN_ / KSPLIT) // 64

// Scratch (no allocations allowed in kernel_launch)
__device__ float g_attn_part[KSPLIT * B_ * ATT_];
__device__ float g_attn_h[B_ * ATT_];
__device__ float g_escores[B_ * S_];      // exp(score), masked -> 0
__device__ float g_partial[NCHUNK * B_ * CTX_];

// ---------------------------------------------------------------------------
// Kernel 1: split-K GEMM partials.
// grid = (ATT/64 = 8 n-tiles, KSPLIT = 16 k-chunks) = 128 blocks.
// ---------------------------------------------------------------------------
#define BM 64
#define BN 64
#define BK 32
__global__ __launch_bounds__(256) void attn_h_kernel(
    const float* __restrict__ h, const float* __restrict__ W) {
    __shared__ float As[BM][BK + 1];
    __shared__ float Bs[BN][BK + 1];
    const int a0 = blockIdx.x * BN;
    const int kbase = blockIdx.y * KCHUNK;
    const int tx = threadIdx.x & 15;   // a sub-tile
    const int ty = threadIdx.x >> 4;   // b sub-tile
    float acc[4][4] = {};

    for (int k0 = kbase; k0 < kbase + KCHUNK; k0 += BK) {
        for (int i = threadIdx.x; i < BM * BK; i += 256) {
            int r = i >> 5, c = i & 31;
            As[r][c] = h[r * RNN_ + k0 + c];
        }
        for (int i = threadIdx.x; i < BN * BK; i += 256) {
            int r = i >> 5, c = i & 31;
            Bs[r][c] = W[(a0 + r) * RNN_ + k0 + c];
        }
        __syncthreads();
#pragma unroll
        for (int k = 0; k < BK; k++) {
            float av[4], bv[4];
#pragma unroll
            for (int i = 0; i < 4; i++) av[i] = As[ty * 4 + i][k];
#pragma unroll
            for (int j = 0; j < 4; j++) bv[j] = Bs[tx * 4 + j][k];
#pragma unroll
            for (int i = 0; i < 4; i++)
#pragma unroll
                for (int j = 0; j < 4; j++)
                    acc[i][j] = fmaf(av[i], bv[j], acc[i][j]);
        }
        __syncthreads();
    }
    float* part = g_attn_part + (size_t)blockIdx.y * B_ * ATT_;
#pragma unroll
    for (int i = 0; i < 4; i++)
#pragma unroll
        for (int j = 0; j < 4; j++)
            part[(ty * 4 + i) * ATT_ + a0 + tx * 4 + j] = acc[i][j];
}

// ---------------------------------------------------------------------------
// Kernel 1b: reduce split-K partials + bias -> attn_h.
// ---------------------------------------------------------------------------
__global__ __launch_bounds__(256) void reduce_attn_kernel(
    const float* __restrict__ bias) {
    const int idx = blockIdx.x * 256 + threadIdx.x;   // 128 blocks
    const int a = idx & (ATT_ - 1);
    float s = bias[a];
#pragma unroll
    for (int k = 0; k < KSPLIT; k++)
        s += g_attn_part[(size_t)k * B_ * ATT_ + idx];
    g_attn_h[idx] = s;
}

// ---------------------------------------------------------------------------
// Accurate fast tanh: 1 - 2/(exp(2x)+1).  Handles +/-inf saturation naturally.
// ---------------------------------------------------------------------------
__device__ __forceinline__ float fast_tanh(float x) {
    float e = __expf(2.0f * x);
    return 1.0f - __fdividef(2.0f, e + 1.0f);
}

// ---------------------------------------------------------------------------
// Kernel 2: e[b,s] = exp(sum_a tanh(pc[b,s,a]+attn_h[b,a])*w_alpha[a] + ba),
//           masked -> 0.  (Max-free softmax numerator: |score| <= 23, so
//           exp is finite in fp32; row sums <= 1.4e13.)
// TWO consecutive rows per warp (same b). mask read as promoted 4-byte bool.
// ---------------------------------------------------------------------------
__global__ __launch_bounds__(256) void scores_kernel(
    const float4* __restrict__ pc, const uint32_t* __restrict__ mask,
    const float4* __restrict__ w_alpha, const float* __restrict__ b_alpha) {
    const int warp = (blockIdx.x * blockDim.x + threadIdx.x) >> 5;
    const int lane = threadIdx.x & 31;
    const int r0   = warp * 2;          // rows r0, r0+1 (always same b)
    const int b    = r0 >> 11;          // S = 2048
    const float4* prow0 = pc + (size_t)r0 * (ATT_ / 4);
    const float4* prow1 = prow0 + (ATT_ / 4);
    const float4* ah    = (const float4*)g_attn_h + b * (ATT_ / 4);
    float sum0 = 0.0f, sum1 = 0.0f;
#pragma unroll
    for (int i = 0; i < 4; i++) {
        int idx = lane + i * 32;
        float4 p0 = __ldcs(prow0 + idx);
        float4 p1 = __ldcs(prow1 + idx);
        float4 a  = ah[idx];
        float4 w  = w_alpha[idx];
        sum0 += fast_tanh(p0.x + a.x) * w.x;
        sum0 += fast_tanh(p0.y + a.y) * w.y;
        sum0 += fast_tanh(p0.z + a.z) * w.z;
        sum0 += fast_tanh(p0.w + a.w) * w.w;
        sum1 += fast_tanh(p1.x + a.x) * w.x;
        sum1 += fast_tanh(p1.y + a.y) * w.y;
        sum1 += fast_tanh(p1.z + a.z) * w.z;
        sum1 += fast_tanh(p1.w + a.w) * w.w;
    }
#pragma unroll
    for (int off = 16; off; off >>= 1) {
        sum0 += __shfl_xor_sync(0xFFFFFFFFu, sum0, off);
        sum1 += __shfl_xor_sync(0xFFFFFFFFu, sum1, off);
    }
    if (lane == 0) {
        float ba = b_alpha[0];
        g_escores[r0]     = (mask[r0]     != 0u) ? 0.0f : expf(sum0 + ba);
        g_escores[r0 + 1] = (mask[r0 + 1] != 0u) ? 0.0f : expf(sum1 + ba);
    }
}

// ---------------------------------------------------------------------------
// Kernel 4 (softmax fused): each block (chunk, b)
//   1. loads the full exp-score row [S] (L2-resident), block-reduces the sum
//   2. normalizes its 64 chunk weights, writes the attn output slice
//   3. streams context[b, s0:s0+SCHUNK, :] and accumulates a [CTX] partial
// ---------------------------------------------------------------------------
__global__ __launch_bounds__(256) void wctx_kernel(
    const float4* __restrict__ context, float* __restrict__ attn_out) {
    const int b = blockIdx.y;
    const int chunk = blockIdx.x;
    const int s0 = chunk * SCHUNK;
    const int t = threadIdx.x;
    const int lane = t & 31, wid = t >> 5;
    const float* row = g_escores + b * S_;

    // --- row sum (deterministic fixed-order tree) ---
    __shared__ float red[8];
    __shared__ float total_sh;
    float part = 0.0f;
#pragma unroll
    for (int i = 0; i < 8; i++)
        part += row[t + i * 256];
#pragma unroll
    for (int off = 16; off; off >>= 1)
        part += __shfl_xor_sync(0xFFFFFFFFu, part, off);
    if (lane == 0) red[wid] = part;
    __syncthreads();
    if (t == 0) {
        float tot = 0.0f;
#pragma unroll
        for (int i = 0; i < 8; i++) tot += red[i];
        total_sh = tot;
    }
    __syncthreads();
    const float total = total_sh;
    const float inv = (total > 0.0f) ? __fdividef(1.0f, total) : 0.0f;

    // --- normalized chunk weights + attn output slice ---
    __shared__ float w[SCHUNK];
    if (t < SCHUNK) {
        float e = row[s0 + t];
        float wt = (total > 0.0f) ? e * inv : (1.0f / S_);  // all-masked: uniform
        w[t] = wt;
        attn_out[b * S_ + s0 + t] = wt;
    }
    __syncthreads();

    // --- weighted context partial ---
    const float4* ctx = context + ((size_t)b * S_ + s0) * (CTX_ / 4);
    float4 acc = make_float4(0.f, 0.f, 0.f, 0.f);
#pragma unroll 8
    for (int s = 0; s < SCHUNK; s++) {
        float4 v = __ldcs(ctx + (size_t)s * (CTX_ / 4) + t);
        float ww = w[s];
        acc.x = fmaf(ww, v.x, acc.x);
        acc.y = fmaf(ww, v.y, acc.y);
        acc.z = fmaf(ww, v.z, acc.z);
        acc.w = fmaf(ww, v.w, acc.w);
    }
    ((float4*)g_partial)[((size_t)chunk * B_ + b) * (CTX_ / 4) + t] = acc;
}

// ---------------------------------------------------------------------------
// Kernel 5: deterministic reduce of the NCHUNK partials -> weighted_context.
// ---------------------------------------------------------------------------
__global__ __launch_bounds__(256) void reduce_kernel(float* __restrict__ wout) {
    const int b = blockIdx.x;
    const int t = threadIdx.x;
    const float4* part = (const float4*)g_partial;
    float4 acc = make_float4(0.f, 0.f, 0.f, 0.f);
#pragma unroll
    for (int c = 0; c < NCHUNK; c++) {
        float4 v = part[((size_t)c * B_ + b) * (CTX_ / 4) + t];
        acc.x += v.x; acc.y += v.y; acc.z += v.z; acc.w += v.w;
    }
    ((float4*)wout)[b * (CTX_ / 4) + t] = acc;
}

// ---------------------------------------------------------------------------
extern "C" void kernel_launch(void* const* d_in, const int* in_sizes, int n_in,
                              void* d_out, int out_size) {
    const float*    h    = (const float*)d_in[0];
    const float*    pc   = (const float*)d_in[1];
    const float*    ctx  = (const float*)d_in[2];
    const uint32_t* mask = (const uint32_t*)d_in[3];
    const float*    W    = (const float*)d_in[4];
    const float*    bh   = (const float*)d_in[5];
    const float*    wa   = (const float*)d_in[6];
    const float*    ba   = (const float*)d_in[7];

    float* out      = (float*)d_out;
    float* wctx_out = out;               // [B, CTX]
    float* attn_out = out + B_ * CTX_;   // [B, S]

    attn_h_kernel<<<dim3(ATT_ / BN, KSPLIT), 256>>>(h, W);
    reduce_attn_kernel<<<(B_ * ATT_) / 256, 256>>>(bh);
    scores_kernel<<<(B_ * S_) / 16, 256>>>((const float4*)pc, mask,
                                           (const float4*)wa, ba);
    wctx_kernel<<<dim3(NCHUNK, B_), 256>>>((const float4*)ctx, attn_out);
    reduce_kernel<<<B_, 256>>>(wctx_out);
}